// round 1
// baseline (speedup 1.0000x reference)
#include <cuda_runtime.h>

#define N2    128
#define MREG  16384
#define START 6
#define TPB   64
#define NBLK  (MREG / TPB)   // 256

__device__ float g_partials[NBLK];

__global__ void __launch_bounds__(TPB) npi_main(
    const float* __restrict__ rt,
    const float* __restrict__ gt,
    const float* __restrict__ SI,
    const float* __restrict__ f,
    const float* __restrict__ seed)
{
    // sSI[k] = SI[k+1]  (shifted so float4 reads from k=0 are 16B-aligned)
    __shared__ __align__(16) float sSI[N2];
    const int tid = threadIdx.x;
    for (int k = tid; k < N2; k += TPB)
        sSI[k] = (k + 1 < N2) ? SI[k + 1] : 0.0f;
    __syncthreads();

    const int m = blockIdx.x * TPB + tid;

    // ---------------- Stage 1: recurrence, pred[] fully in registers ------
    float pred[N2];
#pragma unroll
    for (int i = 0; i < START; ++i)
        pred[i] = seed[i * MREG + m];

#pragma unroll
    for (int i = START; i < N2; ++i) {
        float c0 = 0.f, c1 = 0.f, c2 = 0.f, c3 = 0.f;
        const int full = i & ~3;
#pragma unroll
        for (int dd = 0; dd < full; dd += 4) {
            float4 s = *reinterpret_cast<const float4*>(&sSI[dd]);
            c0 = fmaf(s.x, pred[i - 1 - dd], c0);
            c1 = fmaf(s.y, pred[i - 2 - dd], c1);
            c2 = fmaf(s.z, pred[i - 3 - dd], c2);
            c3 = fmaf(s.w, pred[i - 4 - dd], c3);
        }
#pragma unroll
        for (int dd = full; dd < i; ++dd)
            c0 = fmaf(sSI[dd], pred[i - 1 - dd], c0);
        pred[i] = rt[i * MREG + m] * ((c0 + c1) + (c2 + c3));
    }

    // ---------------- Stage 2: deaths conv (lags >= 2) + MSE --------------
    float loss = 0.0f;
#pragma unroll
    for (int c = 0; c < N2; c += 16) {
        float dth[16];
#pragma unroll
        for (int ii = 0; ii < 16; ++ii) dth[ii] = 0.0f;

        const int dmax = (c + 15 < N2 - 1) ? (c + 15) : (N2 - 1);
#pragma unroll
        for (int d = 2; d <= dmax; ++d) {
            const float fd = f[d * MREG + m];
#pragma unroll
            for (int ii = 0; ii < 16; ++ii) {
                const int i = c + ii;
                if (i >= d) dth[ii] = fmaf(fd, pred[i - d], dth[ii]);
            }
        }

#pragma unroll
        for (int ii = 0; ii < 16; ++ii) {
            const int i = c + ii;
            float dp = dth[ii];
            if (i < START) dp = (i == 0) ? 1e-9f : 0.0f;
            const float diff = dp - gt[i * MREG + m];
            loss = fmaf(diff, diff, loss);
        }
    }

    // ---------------- deterministic reduction -----------------------------
#pragma unroll
    for (int off = 16; off; off >>= 1)
        loss += __shfl_xor_sync(0xffffffffu, loss, off);
    __shared__ float warpsum[TPB / 32];
    if ((tid & 31) == 0) warpsum[tid >> 5] = loss;
    __syncthreads();
    if (tid == 0) {
        float s = 0.0f;
#pragma unroll
        for (int w = 0; w < TPB / 32; ++w) s += warpsum[w];
        g_partials[blockIdx.x] = s;
    }
}

__global__ void __launch_bounds__(256) npi_reduce(float* __restrict__ out)
{
    const int tid = threadIdx.x;
    float v = g_partials[tid];
#pragma unroll
    for (int off = 16; off; off >>= 1)
        v += __shfl_xor_sync(0xffffffffu, v, off);
    __shared__ float ws[8];
    if ((tid & 31) == 0) ws[tid >> 5] = v;
    __syncthreads();
    if (tid == 0) {
        float s = 0.0f;
#pragma unroll
        for (int w = 0; w < 8; ++w) s += ws[w];
        out[0] = s * (1.0f / ((float)N2 * (float)MREG));
    }
}

extern "C" void kernel_launch(void* const* d_in, const int* in_sizes, int n_in,
                              void* d_out, int out_size)
{
    const float* rt   = (const float*)d_in[0];
    const float* gt   = (const float*)d_in[1];
    const float* SI   = (const float*)d_in[2];
    const float* f    = (const float*)d_in[3];
    const float* seed = (const float*)d_in[4];

    npi_main<<<NBLK, TPB>>>(rt, gt, SI, f, seed);
    npi_reduce<<<1, 256>>>((float*)d_out);
}

// round 2
// speedup vs baseline: 1.0091x; 1.0091x over previous
#include <cuda_runtime.h>

#define N2    128
#define MREG  16384
#define START 6
#define TPB   128
#define NBLK  (MREG / TPB)   // 128
#define CH    16

__device__ float        g_partials[NBLK];
__device__ unsigned int g_count = 0;

__global__ void __launch_bounds__(TPB, 1) npi_fused(
    const float* __restrict__ rt,
    const float* __restrict__ gt,
    const float* __restrict__ SI,
    const float* __restrict__ f,
    const float* __restrict__ seed,
    float* __restrict__ out)
{
    // sSI[k] = SI[k+1]  (shift-by-1 so float4 reads at k=0 are 16B aligned)
    __shared__ __align__(16) float sSI[N2];
    const int tid = threadIdx.x;
    if (tid < N2) sSI[tid] = (tid + 1 < N2) ? SI[tid + 1] : 0.0f;
    __syncthreads();

    const int m = blockIdx.x * TPB + tid;

    // ------------- Stage 1: recurrence, pred[] register-resident ----------
    float pred[N2];
#pragma unroll
    for (int i = 0; i < START; ++i)
        pred[i] = seed[i * MREG + m];

#pragma unroll
    for (int i = START; i < N2; ++i) {
        float c0 = 0.f, c1 = 0.f, c2 = 0.f, c3 = 0.f;
#pragma unroll
        for (int dd = 0; dd < (i & ~3); dd += 4) {
            float4 s = *reinterpret_cast<const float4*>(&sSI[dd]);
            c0 = fmaf(s.x, pred[i - 1 - dd], c0);
            c1 = fmaf(s.y, pred[i - 2 - dd], c1);
            c2 = fmaf(s.z, pred[i - 3 - dd], c2);
            c3 = fmaf(s.w, pred[i - 4 - dd], c3);
        }
#pragma unroll
        for (int dd = (i & ~3); dd < i; ++dd)
            c0 = fmaf(sSI[dd], pred[i - 1 - dd], c0);
        pred[i] = rt[i * MREG + m] * ((c0 + c1) + (c2 + c3));
    }

    // ------------- Stage 2: deaths conv (lags >= 2) + MSE -----------------
    // All loop bounds are manifest compile-time constants so every pred[]
    // access is a constant index (no local-memory demotion).
    float loss = 0.0f;
#pragma unroll
    for (int c = 0; c < N2; c += CH) {
        float dth[CH];
#pragma unroll
        for (int ii = 0; ii < CH; ++ii) dth[ii] = 0.0f;

#pragma unroll
        for (int d = 2; d < c + CH; ++d) {       // d <= c+CH-1 == max i in chunk
            const float fd = f[d * MREG + m];
#pragma unroll
            for (int ii = 0; ii < CH; ++ii) {
                const int i = c + ii;
                if (i >= d)                       // compile-time predicate
                    dth[ii] = fmaf(fd, pred[i - d], dth[ii]);
            }
        }

#pragma unroll
        for (int ii = 0; ii < CH; ++ii) {
            const int i = c + ii;
            float dp = dth[ii];
            if (i < START) dp = (i == 0) ? 1e-9f : 0.0f;
            const float diff = dp - gt[i * MREG + m];
            loss = fmaf(diff, diff, loss);
        }
    }

    // ------------- block reduction (deterministic) -------------------------
#pragma unroll
    for (int off = 16; off; off >>= 1)
        loss += __shfl_xor_sync(0xffffffffu, loss, off);

    __shared__ float warpsum[TPB / 32];
    __shared__ bool  s_last;
    if ((tid & 31) == 0) warpsum[tid >> 5] = loss;
    __syncthreads();

    if (tid == 0) {
        float s = 0.0f;
#pragma unroll
        for (int w = 0; w < TPB / 32; ++w) s += warpsum[w];
        g_partials[blockIdx.x] = s;
        __threadfence();
        unsigned prev = atomicAdd(&g_count, 1u);
        s_last = (prev == NBLK - 1u);
    }
    __syncthreads();

    // ------------- last block finishes: fixed-order final sum -------------
    if (s_last) {
        if (tid < 32) {
            float v = 0.0f;
#pragma unroll
            for (int k = 0; k < NBLK / 32; ++k)
                v += g_partials[tid + k * 32];
#pragma unroll
            for (int off = 16; off; off >>= 1)
                v += __shfl_xor_sync(0xffffffffu, v, off);
            if (tid == 0) {
                out[0] = v * (1.0f / ((float)N2 * (float)MREG));
                g_count = 0;   // reset for next (graph-replayed) call
            }
        }
    }
}

extern "C" void kernel_launch(void* const* d_in, const int* in_sizes, int n_in,
                              void* d_out, int out_size)
{
    const float* rt   = (const float*)d_in[0];
    const float* gt   = (const float*)d_in[1];
    const float* SI   = (const float*)d_in[2];
    const float* f    = (const float*)d_in[3];
    const float* seed = (const float*)d_in[4];

    npi_fused<<<NBLK, TPB>>>(rt, gt, SI, f, seed, (float*)d_out);
}

// round 3
// speedup vs baseline: 1.6888x; 1.6736x over previous
#include <cuda_runtime.h>

#define N2    128
#define MREG  16384
#define START 6
#define TPB   64
#define NBLK  (MREG / TPB)   // 256
#define T     16
#define NT    (N2 / T)       // 8

__device__ float        g_partials[NBLK];
__device__ unsigned int g_count = 0;

__global__ void __launch_bounds__(TPB, 1) npi_fused(
    const float* __restrict__ rt,
    const float* __restrict__ gt,
    const float* __restrict__ SI,
    const float* __restrict__ f,
    const float* __restrict__ seed,
    float* __restrict__ out)
{
    __shared__ float sSI[N2];
    __shared__ float sPred[N2][TPB];   // [time][thread] — thread-private columns

    const int tid = threadIdx.x;
    for (int k = tid; k < N2; k += TPB) sSI[k] = SI[k];
    __syncthreads();

    const int m = blockIdx.x * TPB + tid;

    // small SI lags for in-tile triangular solves (uniform across threads)
    float siL[T];
#pragma unroll
    for (int d = 1; d < T; ++d) siL[d] = sSI[d];

    // ================= Stage 1: blocked recurrence =================
    // Tile 0: seeds + triangular
    {
        float pt[T];
#pragma unroll
        for (int ii = 0; ii < START; ++ii) pt[ii] = seed[ii * MREG + m];
        float rtt[T];
#pragma unroll
        for (int ii = START; ii < T; ++ii) rtt[ii] = rt[ii * MREG + m];
#pragma unroll
        for (int ii = START; ii < T; ++ii) {
            float s = 0.f;
#pragma unroll
            for (int jj = 0; jj < T; ++jj)
                if (jj < ii) s = fmaf(siL[ii - jj], pt[jj], s);
            pt[ii] = rtt[ii] * s;
        }
#pragma unroll
        for (int ii = 0; ii < T; ++ii) sPred[ii][tid] = pt[ii];
    }

    // Tiles 1..7: history matvec (register-tiled) + triangular
    for (int I = 1; I < NT; ++I) {
        const int c = I * T;
        float acc[T];
#pragma unroll
        for (int ii = 0; ii < T; ++ii) acc[ii] = 0.f;

        // SI sliding window: for tile-pair (I,J), d = c+ii-jb-jj spans
        // [base, base+30] with base = c-16*J-15; J=I-1 -> base=1.
        float si[31];
#pragma unroll
        for (int k = 0; k < 31; ++k) si[k] = sSI[1 + k];

        for (int J = I - 1; J >= 0; --J) {
            const int jb = J * T;
            float pj[T];
#pragma unroll
            for (int jj = 0; jj < T; ++jj) pj[jj] = sPred[jb + jj][tid];
#pragma unroll
            for (int jj = 0; jj < T; ++jj)
#pragma unroll
                for (int ii = 0; ii < T; ++ii)
                    acc[ii] = fmaf(si[ii - jj + 15], pj[jj], acc[ii]);
            if (J > 0) {
                const int nb = c - (J - 1) * T - 15;   // new window base
#pragma unroll
                for (int k = 0; k < 15; ++k) si[k] = si[k + 16];
#pragma unroll
                for (int k = 15; k < 31; ++k) si[k] = sSI[nb + k];
            }
        }

        float rtt[T];
#pragma unroll
        for (int ii = 0; ii < T; ++ii) rtt[ii] = rt[(c + ii) * MREG + m];
        float pt[T];
#pragma unroll
        for (int ii = 0; ii < T; ++ii) {
            float s = acc[ii];
#pragma unroll
            for (int jj = 0; jj < T; ++jj)
                if (jj < ii) s = fmaf(siL[ii - jj], pt[jj], s);
            pt[ii] = rtt[ii] * s;
            sPred[c + ii][tid] = pt[ii];
        }
    }

    // ================= Stage 2: deaths conv (lags >= 2) + MSE =================
    float fL[T];           // f[2..15] for diagonal tiles
#pragma unroll
    for (int d = 2; d < T; ++d) fL[d] = f[d * MREG + m];

    float loss = 0.f;
    for (int I = 0; I < NT; ++I) {
        const int c = I * T;
        float dth[T];
#pragma unroll
        for (int ii = 0; ii < T; ++ii) dth[ii] = 0.f;

        // diagonal tile: d = ii-jj in [2,15], compile-time predicate
        {
            float pj[T];
#pragma unroll
            for (int jj = 0; jj < T; ++jj) pj[jj] = sPred[c + jj][tid];
#pragma unroll
            for (int jj = 0; jj < T; ++jj)
#pragma unroll
                for (int ii = 0; ii < T; ++ii)
                    if (ii - jj >= 2)
                        dth[ii] = fmaf(fL[ii - jj], pj[jj], dth[ii]);
        }

        if (I > 0) {
            // f sliding window, base=1 for J=I-1; fw[0] (d=1) forced 0 == f_eff
            float fw[31];
            fw[0] = 0.f;
#pragma unroll
            for (int k = 1; k < 31; ++k) fw[k] = f[(1 + k) * MREG + m];
            for (int J = I - 1; J >= 0; --J) {
                const int jb = J * T;
                float pj[T];
#pragma unroll
                for (int jj = 0; jj < T; ++jj) pj[jj] = sPred[jb + jj][tid];
#pragma unroll
                for (int jj = 0; jj < T; ++jj)
#pragma unroll
                    for (int ii = 0; ii < T; ++ii)
                        dth[ii] = fmaf(fw[ii - jj + 15], pj[jj], dth[ii]);
                if (J > 0) {
                    const int nb = c - (J - 1) * T - 15;
#pragma unroll
                    for (int k = 0; k < 15; ++k) fw[k] = fw[k + 16];
#pragma unroll
                    for (int k = 15; k < 31; ++k) fw[k] = f[(nb + k) * MREG + m];
                }
            }
        }

        float gtt[T];
#pragma unroll
        for (int ii = 0; ii < T; ++ii) gtt[ii] = gt[(c + ii) * MREG + m];
#pragma unroll
        for (int ii = 0; ii < T; ++ii) {
            float dp = dth[ii];
            if (c + ii < START) dp = (c + ii == 0) ? 1e-9f : 0.f;
            const float diff = dp - gtt[ii];
            loss = fmaf(diff, diff, loss);
        }
    }

    // ================= deterministic fused reduction =================
#pragma unroll
    for (int off = 16; off; off >>= 1)
        loss += __shfl_xor_sync(0xffffffffu, loss, off);

    __shared__ float warpsum[TPB / 32];
    __shared__ bool  s_last;
    if ((tid & 31) == 0) warpsum[tid >> 5] = loss;
    __syncthreads();

    if (tid == 0) {
        float s = 0.0f;
#pragma unroll
        for (int w = 0; w < TPB / 32; ++w) s += warpsum[w];
        g_partials[blockIdx.x] = s;
        __threadfence();
        unsigned prev = atomicAdd(&g_count, 1u);
        s_last = (prev == NBLK - 1u);
    }
    __syncthreads();

    if (s_last) {
        if (tid < 32) {
            float v = 0.0f;
#pragma unroll
            for (int k = 0; k < NBLK / 32; ++k)
                v += g_partials[tid + k * 32];
#pragma unroll
            for (int off = 16; off; off >>= 1)
                v += __shfl_xor_sync(0xffffffffu, v, off);
            if (tid == 0) {
                out[0] = v * (1.0f / ((float)N2 * (float)MREG));
                g_count = 0;   // reset for graph replay
            }
        }
    }
}

extern "C" void kernel_launch(void* const* d_in, const int* in_sizes, int n_in,
                              void* d_out, int out_size)
{
    const float* rt   = (const float*)d_in[0];
    const float* gt   = (const float*)d_in[1];
    const float* SI   = (const float*)d_in[2];
    const float* f    = (const float*)d_in[3];
    const float* seed = (const float*)d_in[4];

    npi_fused<<<NBLK, TPB>>>(rt, gt, SI, f, seed, (float*)d_out);
}

// round 4
// speedup vs baseline: 1.7018x; 1.0077x over previous
#include <cuda_runtime.h>

#define N2    128
#define MREG  16384
#define START 6
#define TPB   128
#define NBLK  (MREG / TPB)   // 128
#define T     16
#define NT    (N2 / T)       // 8

__device__ float        g_partials[NBLK];
__device__ unsigned int g_count = 0;

__global__ void __launch_bounds__(TPB, 1) npi_fused(
    const float* __restrict__ rt,
    const float* __restrict__ gt,
    const float* __restrict__ SI,
    const float* __restrict__ f,
    const float* __restrict__ seed,
    float* __restrict__ out)
{
    __shared__ float sSI[N2];
    __shared__ float sPred[N2][TPB];   // [time][thread] — thread-private columns

    const int tid = threadIdx.x;
    if (tid < N2) sSI[tid] = SI[tid];
    __syncthreads();

    const int m = blockIdx.x * TPB + tid;

    // small SI lags for in-tile triangular solves (uniform across threads)
    float siL[T];
#pragma unroll
    for (int d = 1; d < T; ++d) siL[d] = sSI[d];

    // ================= Stage 1: blocked recurrence =================
    // Tile 0: seeds + triangular
    {
        float pt[T];
#pragma unroll
        for (int ii = 0; ii < START; ++ii) pt[ii] = seed[ii * MREG + m];
        float rtt[T];
#pragma unroll
        for (int ii = START; ii < T; ++ii) rtt[ii] = rt[ii * MREG + m];
#pragma unroll
        for (int ii = START; ii < T; ++ii) {
            float s = 0.f;
#pragma unroll
            for (int jj = 0; jj < T; ++jj)
                if (jj < ii) s = fmaf(siL[ii - jj], pt[jj], s);
            pt[ii] = rtt[ii] * s;
        }
#pragma unroll
        for (int ii = 0; ii < T; ++ii) sPred[ii][tid] = pt[ii];
    }

    // Tiles 1..7: history matvec (register-tiled) + triangular
    for (int I = 1; I < NT; ++I) {
        const int c = I * T;
        float acc[T];
#pragma unroll
        for (int ii = 0; ii < T; ++ii) acc[ii] = 0.f;

        // SI sliding window: for tile-pair (I,J), d = c+ii-jb-jj spans
        // [base, base+30] with base = c-16*J-15; J=I-1 -> base=1.
        float si[31];
#pragma unroll
        for (int k = 0; k < 31; ++k) si[k] = sSI[1 + k];

        for (int J = I - 1; J >= 0; --J) {
            const int jb = J * T;
            float pj[T];
#pragma unroll
            for (int jj = 0; jj < T; ++jj) pj[jj] = sPred[jb + jj][tid];
#pragma unroll
            for (int jj = 0; jj < T; ++jj)
#pragma unroll
                for (int ii = 0; ii < T; ++ii)
                    acc[ii] = fmaf(si[ii - jj + 15], pj[jj], acc[ii]);
            if (J > 0) {
                const int nb = c - (J - 1) * T - 15;   // new window base
#pragma unroll
                for (int k = 0; k < 15; ++k) si[k] = si[k + 16];
#pragma unroll
                for (int k = 15; k < 31; ++k) si[k] = sSI[nb + k];
            }
        }

        float rtt[T];
#pragma unroll
        for (int ii = 0; ii < T; ++ii) rtt[ii] = rt[(c + ii) * MREG + m];
        float pt[T];
#pragma unroll
        for (int ii = 0; ii < T; ++ii) {
            float s = acc[ii];
#pragma unroll
            for (int jj = 0; jj < T; ++jj)
                if (jj < ii) s = fmaf(siL[ii - jj], pt[jj], s);
            pt[ii] = rtt[ii] * s;
            sPred[c + ii][tid] = pt[ii];
        }
    }

    // ================= Stage 2: deaths conv (lags >= 2) + MSE =================
    float fL[T];           // f[2..15] for diagonal tiles
#pragma unroll
    for (int d = 2; d < T; ++d) fL[d] = f[d * MREG + m];

    float loss = 0.f;
    for (int I = 0; I < NT; ++I) {
        const int c = I * T;
        float dth[T];
#pragma unroll
        for (int ii = 0; ii < T; ++ii) dth[ii] = 0.f;

        // diagonal tile: d = ii-jj in [2,15], compile-time predicate
        {
            float pj[T];
#pragma unroll
            for (int jj = 0; jj < T; ++jj) pj[jj] = sPred[c + jj][tid];
#pragma unroll
            for (int jj = 0; jj < T; ++jj)
#pragma unroll
                for (int ii = 0; ii < T; ++ii)
                    if (ii - jj >= 2)
                        dth[ii] = fmaf(fL[ii - jj], pj[jj], dth[ii]);
        }

        if (I > 0) {
            // f sliding window, base=1 for J=I-1; fw[0] (d=1) forced 0 == f_eff
            float fw[31];
            fw[0] = 0.f;
#pragma unroll
            for (int k = 1; k < 31; ++k) fw[k] = f[(1 + k) * MREG + m];
            for (int J = I - 1; J >= 0; --J) {
                const int jb = J * T;
                float pj[T];
#pragma unroll
                for (int jj = 0; jj < T; ++jj) pj[jj] = sPred[jb + jj][tid];
#pragma unroll
                for (int jj = 0; jj < T; ++jj)
#pragma unroll
                    for (int ii = 0; ii < T; ++ii)
                        dth[ii] = fmaf(fw[ii - jj + 15], pj[jj], dth[ii]);
                if (J > 0) {
                    const int nb = c - (J - 1) * T - 15;
#pragma unroll
                    for (int k = 0; k < 15; ++k) fw[k] = fw[k + 16];
#pragma unroll
                    for (int k = 15; k < 31; ++k) fw[k] = f[(nb + k) * MREG + m];
                }
            }
        }

        float gtt[T];
#pragma unroll
        for (int ii = 0; ii < T; ++ii) gtt[ii] = gt[(c + ii) * MREG + m];
#pragma unroll
        for (int ii = 0; ii < T; ++ii) {
            float dp = dth[ii];
            if (c + ii < START) dp = (c + ii == 0) ? 1e-9f : 0.f;
            const float diff = dp - gtt[ii];
            loss = fmaf(diff, diff, loss);
        }
    }

    // ================= deterministic fused reduction =================
#pragma unroll
    for (int off = 16; off; off >>= 1)
        loss += __shfl_xor_sync(0xffffffffu, loss, off);

    __shared__ float warpsum[TPB / 32];
    __shared__ bool  s_last;
    if ((tid & 31) == 0) warpsum[tid >> 5] = loss;
    __syncthreads();

    if (tid == 0) {
        float s = 0.0f;
#pragma unroll
        for (int w = 0; w < TPB / 32; ++w) s += warpsum[w];
        g_partials[blockIdx.x] = s;
        __threadfence();
        unsigned prev = atomicAdd(&g_count, 1u);
        s_last = (prev == NBLK - 1u);
    }
    __syncthreads();

    if (s_last) {
        if (tid < 32) {
            float v = 0.0f;
#pragma unroll
            for (int k = 0; k < NBLK / 32; ++k)
                v += g_partials[tid + k * 32];
#pragma unroll
            for (int off = 16; off; off >>= 1)
                v += __shfl_xor_sync(0xffffffffu, v, off);
            if (tid == 0) {
                out[0] = v * (1.0f / ((float)N2 * (float)MREG));
                g_count = 0;   // reset for graph replay
            }
        }
    }
}

extern "C" void kernel_launch(void* const* d_in, const int* in_sizes, int n_in,
                              void* d_out, int out_size)
{
    const float* rt   = (const float*)d_in[0];
    const float* gt   = (const float*)d_in[1];
    const float* SI   = (const float*)d_in[2];
    const float* f    = (const float*)d_in[3];
    const float* seed = (const float*)d_in[4];

    npi_fused<<<NBLK, TPB>>>(rt, gt, SI, f, seed, (float*)d_out);
}

// round 5
// speedup vs baseline: 1.9821x; 1.1648x over previous
#include <cuda_runtime.h>

#define N2    128
#define MREG  16384
#define START 6
#define TPB   128
#define NBLK  (MREG / TPB)   // 128
#define T     16
#define NT    (N2 / T)       // 8

#define SMEM_FLOATS (N2 + 2 * N2 * TPB)
#define SMEM_BYTES  (SMEM_FLOATS * sizeof(float))

__device__ float        g_partials[NBLK];
__device__ unsigned int g_count = 0;

__global__ void __launch_bounds__(TPB, 1) npi_fused(
    const float* __restrict__ rt,
    const float* __restrict__ gt,
    const float* __restrict__ SI,
    const float* __restrict__ f,
    const float* __restrict__ seed,
    float* __restrict__ out)
{
    extern __shared__ float smem[];
    float* sSI   = smem;                 // [N2]
    float* sPred = smem + N2;            // [N2][TPB]
    float* sF    = sPred + N2 * TPB;     // [N2][TPB]

    const int tid = threadIdx.x;
    const int m   = blockIdx.x * TPB + tid;

    if (tid < N2) sSI[tid] = SI[tid];
    // stage f into smem once: 128 coalesced LDGs, high MLP
#pragma unroll 8
    for (int k = 0; k < N2; ++k)
        sF[k * TPB + tid] = f[k * MREG + m];
    __syncthreads();

    float siL[T];
#pragma unroll
    for (int d = 1; d < T; ++d) siL[d] = sSI[d];

    // ================= Stage 1: blocked recurrence =================
    // Tile 0: seeds + forward-substitution triangular
    {
        float rtt[T];
#pragma unroll
        for (int ii = START; ii < T; ++ii) rtt[ii] = rt[ii * MREG + m];
        float pt[T], s[T];
#pragma unroll
        for (int ii = 0; ii < START; ++ii) pt[ii] = seed[ii * MREG + m];
#pragma unroll
        for (int ii = START; ii < T; ++ii) s[ii] = 0.f;
#pragma unroll
        for (int jj = 0; jj < T; ++jj) {
            if (jj >= START) pt[jj] = rtt[jj] * s[jj];
#pragma unroll
            for (int ii = (jj + 1 > START ? jj + 1 : START); ii < T; ++ii)
                s[ii] = fmaf(siL[ii - jj], pt[jj], s[ii]);
        }
#pragma unroll
        for (int ii = 0; ii < T; ++ii) sPred[ii * TPB + tid] = pt[ii];
    }

    // Tiles 1..7
    for (int I = 1; I < NT; ++I) {
        const int c = I * T;
        float rtt[T];                       // prefetch early, hidden by matvec
#pragma unroll
        for (int ii = 0; ii < T; ++ii) rtt[ii] = rt[(c + ii) * MREG + m];

        float acc[T];
#pragma unroll
        for (int ii = 0; ii < T; ++ii) acc[ii] = 0.f;

        float si[31];                       // window base = 1 for J=I-1
#pragma unroll
        for (int k = 0; k < 31; ++k) si[k] = sSI[1 + k];

        for (int J = I - 1; J >= 0; --J) {
            const int jb = J * T;
            float pj[T];
#pragma unroll
            for (int jj = 0; jj < T; ++jj) pj[jj] = sPred[(jb + jj) * TPB + tid];
#pragma unroll
            for (int jj = 0; jj < T; ++jj)
#pragma unroll
                for (int ii = 0; ii < T; ++ii)
                    acc[ii] = fmaf(si[ii - jj + 15], pj[jj], acc[ii]);
            if (J > 0) {
                const int nb = c - (J - 1) * T - 15;
#pragma unroll
                for (int k = 0; k < 15; ++k) si[k] = si[k + 16];
#pragma unroll
                for (int k = 15; k < 31; ++k) si[k] = sSI[nb + k];
            }
        }

        // forward-substitution triangular (same FP order as serial version)
        float pt[T];
#pragma unroll
        for (int jj = 0; jj < T; ++jj) {
            pt[jj] = rtt[jj] * acc[jj];
#pragma unroll
            for (int ii = jj + 1; ii < T; ++ii)
                acc[ii] = fmaf(siL[ii - jj], pt[jj], acc[ii]);
        }
#pragma unroll
        for (int ii = 0; ii < T; ++ii) sPred[(c + ii) * TPB + tid] = pt[ii];
    }

    // ================= Stage 2: deaths conv (lags >= 2) + MSE =================
    float fL[T];
#pragma unroll
    for (int d = 2; d < T; ++d) fL[d] = sF[d * TPB + tid];

    float loss = 0.f;
    for (int I = 0; I < NT; ++I) {
        const int c = I * T;
        float gtt[T];                       // prefetch early
#pragma unroll
        for (int ii = 0; ii < T; ++ii) gtt[ii] = gt[(c + ii) * MREG + m];

        float dth[T];
#pragma unroll
        for (int ii = 0; ii < T; ++ii) dth[ii] = 0.f;

        { // diagonal tile: d = ii-jj in [2,15]
            float pj[T];
#pragma unroll
            for (int jj = 0; jj < T; ++jj) pj[jj] = sPred[(c + jj) * TPB + tid];
#pragma unroll
            for (int jj = 0; jj < T; ++jj)
#pragma unroll
                for (int ii = 0; ii < T; ++ii)
                    if (ii - jj >= 2)
                        dth[ii] = fmaf(fL[ii - jj], pj[jj], dth[ii]);
        }

        if (I > 0) {
            float fw[31];                   // window base = 1; fw[0] == f_eff[1] = 0
            fw[0] = 0.f;
#pragma unroll
            for (int k = 1; k < 31; ++k) fw[k] = sF[(1 + k) * TPB + tid];
            for (int J = I - 1; J >= 0; --J) {
                const int jb = J * T;
                float pj[T];
#pragma unroll
                for (int jj = 0; jj < T; ++jj) pj[jj] = sPred[(jb + jj) * TPB + tid];
#pragma unroll
                for (int jj = 0; jj < T; ++jj)
#pragma unroll
                    for (int ii = 0; ii < T; ++ii)
                        dth[ii] = fmaf(fw[ii - jj + 15], pj[jj], dth[ii]);
                if (J > 0) {
                    const int nb = c - (J - 1) * T - 15;
#pragma unroll
                    for (int k = 0; k < 15; ++k) fw[k] = fw[k + 16];
#pragma unroll
                    for (int k = 15; k < 31; ++k) fw[k] = sF[(nb + k) * TPB + tid];
                }
            }
        }

#pragma unroll
        for (int ii = 0; ii < T; ++ii) {
            float dp = dth[ii];
            if (c + ii < START) dp = (c + ii == 0) ? 1e-9f : 0.f;
            const float diff = dp - gtt[ii];
            loss = fmaf(diff, diff, loss);
        }
    }

    // ================= deterministic fused reduction =================
#pragma unroll
    for (int off = 16; off; off >>= 1)
        loss += __shfl_xor_sync(0xffffffffu, loss, off);

    __shared__ float warpsum[TPB / 32];
    __shared__ bool  s_last;
    if ((tid & 31) == 0) warpsum[tid >> 5] = loss;
    __syncthreads();

    if (tid == 0) {
        float s = 0.0f;
#pragma unroll
        for (int w = 0; w < TPB / 32; ++w) s += warpsum[w];
        g_partials[blockIdx.x] = s;
        __threadfence();
        unsigned prev = atomicAdd(&g_count, 1u);
        s_last = (prev == NBLK - 1u);
    }
    __syncthreads();

    if (s_last) {
        if (tid < 32) {
            float v = 0.0f;
#pragma unroll
            for (int k = 0; k < NBLK / 32; ++k)
                v += g_partials[tid + k * 32];
#pragma unroll
            for (int off = 16; off; off >>= 1)
                v += __shfl_xor_sync(0xffffffffu, v, off);
            if (tid == 0) {
                out[0] = v * (1.0f / ((float)N2 * (float)MREG));
                g_count = 0;   // reset for graph replay
            }
        }
    }
}

extern "C" void kernel_launch(void* const* d_in, const int* in_sizes, int n_in,
                              void* d_out, int out_size)
{
    const float* rt   = (const float*)d_in[0];
    const float* gt   = (const float*)d_in[1];
    const float* SI   = (const float*)d_in[2];
    const float* f    = (const float*)d_in[3];
    const float* seed = (const float*)d_in[4];

    static bool attr_set = false;
    if (!attr_set) {
        cudaFuncSetAttribute(npi_fused,
                             cudaFuncAttributeMaxDynamicSharedMemorySize,
                             SMEM_BYTES);
        attr_set = true;
    }

    npi_fused<<<NBLK, TPB, SMEM_BYTES>>>(rt, gt, SI, f, seed, (float*)d_out);
}